// round 2
// baseline (speedup 1.0000x reference)
#include <cuda_runtime.h>

// WindowAttention fused SIMT fp32 baseline.
// 1 CTA per window (8192 CTAs, 256 threads). All intermediates in SMEM.
//
// Per-CTA flow:
//   P0: load x[64x256], mask[64x64], rel_idx[64x64] to SMEM
//   per head h (8):
//     P1: QKV_h[64x96] = x @ W_h^T + b_h   (W_h = 32 rows of wq + 32 k-rows + 32 v-rows of wkv)
//     P2: S[64x64] = Q_h K_h^T
//     P3: softmax rows with SCALE, rel-pos bias gather, window mask
//     P4: O_h[64x32] = P V_h  -> Obuf[:, h*32:(h+1)*32]
//   P5: out[64x256] = Obuf @ wp^T + bp

#define NTOK   64
#define CDIM   256
#define HEADS  8
#define HDIM   32
#define NWIN   4096
#define ATTN_SCALE 0.17677669529663687f   // 32^-0.5

// SMEM float offsets / pitches (bank-conflict tuned)
#define XS_PITCH 260
#define OB_PITCH 260
#define WS_PITCH 33
#define QK_PITCH 101
#define SS_PITCH 66
#define MK_PITCH 65
#define RI_PITCH 65

#define XS_OFF 0
#define OB_OFF (XS_OFF + 64 * XS_PITCH)
#define WS_OFF (OB_OFF + 64 * OB_PITCH)
#define QK_OFF (WS_OFF + 128 * WS_PITCH)
#define SS_OFF (QK_OFF + 64 * QK_PITCH)
#define MK_OFF (SS_OFF + 64 * SS_PITCH)
#define RI_OFF (MK_OFF + 64 * MK_PITCH)
#define SMEM_FLOATS (RI_OFF + 64 * RI_PITCH)
#define SMEM_BYTES  (SMEM_FLOATS * 4)

__global__ __launch_bounds__(256, 1)
void winattn_kernel(const float* __restrict__ x,
                    const float* __restrict__ mask,
                    const float* __restrict__ wq,  const float* __restrict__ bq,
                    const float* __restrict__ wkv, const float* __restrict__ bkv,
                    const float* __restrict__ wp,  const float* __restrict__ bp,
                    const float* __restrict__ btab,
                    const int*   __restrict__ ridx,
                    float* __restrict__ out)
{
    extern __shared__ float sm[];
    float* xs = sm + XS_OFF;   // x window       [64][260]
    float* ob = sm + OB_OFF;   // attention out  [64][260]
    float* ws = sm + WS_OFF;   // weight k-chunk [128][33]
    float* qk = sm + QK_OFF;   // q|k|v head     [64][101]
    float* ss = sm + SS_OFF;   // scores/probs   [64][66]
    float* mk = sm + MK_OFF;   // window mask    [64][65]
    int*   ri = (int*)(sm + RI_OFF); // rel idx  [64][65]

    const int tid = threadIdx.x;
    const int b   = blockIdx.x;
    const int ty  = tid >> 4;   // 0..15
    const int tx  = tid & 15;   // 0..15

    // ---------- P0: stage inputs ----------
    const float4* x4 = (const float4*)(x + (size_t)b * NTOK * CDIM);
    for (int i = tid; i < NTOK * (CDIM / 4); i += 256) {
        int t = i >> 6, c4 = i & 63;
        float4 v = x4[i];
        float* d = xs + t * XS_PITCH + c4 * 4;
        d[0] = v.x; d[1] = v.y; d[2] = v.z; d[3] = v.w;
    }
    const float* mrow = mask + (size_t)(b & (NWIN - 1)) * NTOK * NTOK;
    for (int i = tid; i < NTOK * NTOK; i += 256) {
        int n = i >> 6, m = i & 63;
        mk[n * MK_PITCH + m] = mrow[i];
        ri[n * RI_PITCH + m] = ridx[i];
    }
    __syncthreads();

    // ---------- per-head loop ----------
    for (int h = 0; h < HEADS; h++) {
        // ---- P1: QKV_h = x @ W_h^T ----
        float acc[4][6];
        #pragma unroll
        for (int i = 0; i < 4; i++)
            #pragma unroll
            for (int j = 0; j < 6; j++) acc[i][j] = 0.f;

        for (int kc = 0; kc < 8; kc++) {
            __syncthreads();   // prior consumers of ws done
            for (int i = tid; i < 96 * 32; i += 256) {
                int r = i >> 5, kk = i & 31;
                const float* wrow;
                if (r < 32)      wrow = wq  + (size_t)(h * HDIM + r) * CDIM;
                else if (r < 64) wrow = wkv + (size_t)(h * HDIM + r - 32) * CDIM;
                else             wrow = wkv + (size_t)(CDIM + h * HDIM + r - 64) * CDIM;
                ws[r * WS_PITCH + kk] = wrow[kc * 32 + kk];
            }
            __syncthreads();
            #pragma unroll 4
            for (int kk = 0; kk < 32; kk++) {
                float a[4], bb[6];
                #pragma unroll
                for (int i = 0; i < 4; i++)
                    a[i] = xs[(ty * 4 + i) * XS_PITCH + kc * 32 + kk];
                #pragma unroll
                for (int j = 0; j < 6; j++)
                    bb[j] = ws[(tx * 6 + j) * WS_PITCH + kk];
                #pragma unroll
                for (int i = 0; i < 4; i++)
                    #pragma unroll
                    for (int j = 0; j < 6; j++)
                        acc[i][j] = fmaf(a[i], bb[j], acc[i][j]);
            }
        }
        // write q|k|v (+bias) into qk
        #pragma unroll
        for (int j = 0; j < 6; j++) {
            int o = tx * 6 + j;
            float bias;
            if (o < 32)      bias = __ldg(bq  + h * HDIM + o);
            else if (o < 64) bias = __ldg(bkv + h * HDIM + o - 32);
            else             bias = __ldg(bkv + CDIM + h * HDIM + o - 64);
            #pragma unroll
            for (int i = 0; i < 4; i++)
                qk[(ty * 4 + i) * QK_PITCH + o] = acc[i][j] + bias;
        }
        __syncthreads();

        // ---- P2: scores S = Q K^T ----
        {
            float sc[4][4];
            #pragma unroll
            for (int i = 0; i < 4; i++)
                #pragma unroll
                for (int j = 0; j < 4; j++) sc[i][j] = 0.f;
            #pragma unroll 4
            for (int d = 0; d < 32; d++) {
                float a[4], bb[4];
                #pragma unroll
                for (int i = 0; i < 4; i++)
                    a[i] = qk[(ty * 4 + i) * QK_PITCH + d];
                #pragma unroll
                for (int j = 0; j < 4; j++)
                    bb[j] = qk[(tx * 4 + j) * QK_PITCH + 32 + d];
                #pragma unroll
                for (int i = 0; i < 4; i++)
                    #pragma unroll
                    for (int j = 0; j < 4; j++)
                        sc[i][j] = fmaf(a[i], bb[j], sc[i][j]);
            }
            #pragma unroll
            for (int i = 0; i < 4; i++)
                #pragma unroll
                for (int j = 0; j < 4; j++)
                    ss[(ty * 4 + i) * SS_PITCH + tx * 4 + j] = sc[i][j];
        }
        __syncthreads();

        // ---- P3: softmax rows (scale + bias + mask) ----
        if (tid < 64) {
            int n = tid;
            float*       srow = ss + n * SS_PITCH;
            const float* mrw  = mk + n * MK_PITCH;
            const int*   rrw  = ri + n * RI_PITCH;
            float mx = -1e30f;
            #pragma unroll 8
            for (int m = 0; m < 64; m++) {
                float v = fmaf(srow[m], ATTN_SCALE,
                               __ldg(btab + rrw[m] * HEADS + h) + mrw[m]);
                srow[m] = v;
                mx = fmaxf(mx, v);
            }
            float s = 0.f;
            #pragma unroll 8
            for (int m = 0; m < 64; m++) {
                float p = __expf(srow[m] - mx);
                srow[m] = p;
                s += p;
            }
            float inv = 1.f / s;
            #pragma unroll 8
            for (int m = 0; m < 64; m++)
                srow[m] *= inv;
        }
        __syncthreads();

        // ---- P4: O_h = P @ V_h ----
        {
            int n  = tid >> 2;
            int d0 = (tid & 3) * 8;
            float av[8];
            #pragma unroll
            for (int j = 0; j < 8; j++) av[j] = 0.f;
            #pragma unroll 4
            for (int k = 0; k < 64; k++) {
                float p = ss[n * SS_PITCH + k];
                #pragma unroll
                for (int j = 0; j < 8; j++)
                    av[j] = fmaf(p, qk[k * QK_PITCH + 64 + d0 + j], av[j]);
            }
            #pragma unroll
            for (int j = 0; j < 8; j++)
                ob[n * OB_PITCH + h * HDIM + d0 + j] = av[j];
        }
        __syncthreads();
    }

    // ---------- P5: out = Obuf @ wp^T + bp ----------
    for (int oc = 0; oc < 2; oc++) {
        float acc2[4][8];
        #pragma unroll
        for (int i = 0; i < 4; i++)
            #pragma unroll
            for (int j = 0; j < 8; j++) acc2[i][j] = 0.f;

        for (int kc = 0; kc < 8; kc++) {
            __syncthreads();
            for (int i = tid; i < 128 * 32; i += 256) {
                int r = i >> 5, kk = i & 31;
                ws[r * WS_PITCH + kk] = wp[(size_t)(oc * 128 + r) * CDIM + kc * 32 + kk];
            }
            __syncthreads();
            #pragma unroll 4
            for (int kk = 0; kk < 32; kk++) {
                float a[4], bb[8];
                #pragma unroll
                for (int i = 0; i < 4; i++)
                    a[i] = ob[(ty * 4 + i) * OB_PITCH + kc * 32 + kk];
                #pragma unroll
                for (int j = 0; j < 8; j++)
                    bb[j] = ws[(tx + j * 16) * WS_PITCH + kk];
                #pragma unroll
                for (int i = 0; i < 4; i++)
                    #pragma unroll
                    for (int j = 0; j < 8; j++)
                        acc2[i][j] = fmaf(a[i], bb[j], acc2[i][j]);
            }
        }
        float* orow = out + (size_t)b * NTOK * CDIM;
        #pragma unroll
        for (int j = 0; j < 8; j++) {
            int c = oc * 128 + tx + j * 16;
            float bias = __ldg(bp + c);
            #pragma unroll
            for (int i = 0; i < 4; i++)
                orow[(ty * 4 + i) * CDIM + c] = acc2[i][j] + bias;
        }
    }
}

extern "C" void kernel_launch(void* const* d_in, const int* in_sizes, int n_in,
                              void* d_out, int out_size)
{
    const float* x    = (const float*)d_in[0];
    const float* mask = (const float*)d_in[1];
    const float* wq   = (const float*)d_in[2];
    const float* bq   = (const float*)d_in[3];
    const float* wkv  = (const float*)d_in[4];
    const float* bkv  = (const float*)d_in[5];
    const float* wp   = (const float*)d_in[6];
    const float* bp   = (const float*)d_in[7];
    const float* bt   = (const float*)d_in[8];
    const int*   ri   = (const int*)d_in[9];
    float* out = (float*)d_out;

    cudaFuncSetAttribute(winattn_kernel,
                         cudaFuncAttributeMaxDynamicSharedMemorySize, SMEM_BYTES);
    winattn_kernel<<<8192, 256, SMEM_BYTES>>>(x, mask, wq, bq, wkv, bkv, wp, bp, bt, ri, out);
}

// round 4
// speedup vs baseline: 2.6445x; 2.6445x over previous
#include <cuda_runtime.h>
#include <mma.h>
#include <cstdint>
using namespace nvcuda;

#define SCALE_F 0.17677669529663687f   // 32^-0.5

// smem pitches (floats, all multiples of 8 for wmma ldm)
#define XP  264
#define OBP 264
#define WSP 40
#define QKP 104
#define SSP 72
#define MKP 65

#define XS_OFF 0
#define OB_OFF (XS_OFF + 64 * XP)        // 16896
#define WS_OFF (OB_OFF + 64 * OBP)       // 33792
#define QK_OFF (WS_OFF + 128 * WSP)      // 38912
#define SS_OFF (QK_OFF + 64 * QKP)       // 45568
#define MK_OFF (SS_OFF + 64 * SSP)       // 50176
#define RI_OFF (MK_OFF + 64 * MKP)       // 54336 (u8 region, 64*65 bytes)
#define SMEM_FLOATS (RI_OFF + 1040)
#define SMEM_BYTES  (SMEM_FLOATS * 4)    // 221504

// round f32 -> tf32 (rna), keep in f32 container
__device__ __forceinline__ float tfr(float f) {
    uint32_t u;
    asm("cvt.rna.tf32.f32 %0, %1;" : "=r"(u) : "f"(f));
    return __uint_as_float(u);
}

typedef wmma::fragment<wmma::matrix_a, 16, 16, 8, wmma::precision::tf32, wmma::row_major> FragA;
typedef wmma::fragment<wmma::matrix_b, 16, 16, 8, wmma::precision::tf32, wmma::col_major> FragBc;
typedef wmma::fragment<wmma::matrix_b, 16, 16, 8, wmma::precision::tf32, wmma::row_major> FragBr;
typedef wmma::fragment<wmma::accumulator, 16, 16, 8, float> FragC;

__global__ __launch_bounds__(256, 1)
void winattn_wmma(const float* __restrict__ x,    const float* __restrict__ mask,
                  const float* __restrict__ wq,   const float* __restrict__ bq,
                  const float* __restrict__ wkv,  const float* __restrict__ bkv,
                  const float* __restrict__ wp,   const float* __restrict__ bp,
                  const float* __restrict__ btab, const int* __restrict__ ridx,
                  float* __restrict__ out)
{
    extern __shared__ float sm[];
    float*   xs = sm + XS_OFF;   // X [64][264], later out staging
    float*   ob = sm + OB_OFF;   // attn out [64][264]
    float*   ws = sm + WS_OFF;   // weight chunk [<=128][40]
    float*   qk = sm + QK_OFF;   // q|k|v head [64][104]
    float*   ss = sm + SS_OFF;   // scores/probs [64][72]
    float*   mk = sm + MK_OFF;   // mask [64][65]
    uint8_t* ri = (uint8_t*)(sm + RI_OFF); // rel idx u8 [64][65]

    const int tid  = threadIdx.x;
    const int w    = tid >> 5;
    const int b    = blockIdx.x;

    // ---------- stage inputs ----------
    const float4* xg = (const float4*)(x + (size_t)b * 16384);
    #pragma unroll
    for (int i = 0; i < 16; i++) {
        int idx = tid + 256 * i;
        int t = idx >> 6, c4 = idx & 63;
        float4 v = xg[idx];
        float* d = xs + t * XP + c4 * 4;
        d[0] = tfr(v.x); d[1] = tfr(v.y); d[2] = tfr(v.z); d[3] = tfr(v.w);
    }
    const float* mg = mask + (size_t)(b & 4095) * 4096;
    #pragma unroll
    for (int i = 0; i < 16; i++) {
        int idx = tid + 256 * i;
        int n = idx >> 6, m = idx & 63;
        mk[n * MKP + m] = mg[idx];
        ri[n * 65 + m]  = (uint8_t)ridx[idx];
    }
    __syncthreads();

    // ---------- per-head ----------
    for (int h = 0; h < 8; h++) {
        // ---- GEMM1: QKV_h[64,96] = X @ W_h^T ----
        FragC acc[3];
        #pragma unroll
        for (int j = 0; j < 3; j++) wmma::fill_fragment(acc[j], 0.f);

        for (int kc = 0; kc < 8; kc++) {
            __syncthreads();
            #pragma unroll
            for (int i = 0; i < 3; i++) {              // 96 rows x 32 cols
                int idx = tid + 256 * i;
                int f = idx >> 3, c4 = idx & 7;
                const float* wrow =
                    (f < 32) ? wq  + (size_t)(h * 32 + f) * 256 :
                    (f < 64) ? wkv + (size_t)(h * 32 + f - 32) * 256
                             : wkv + (size_t)(256 + h * 32 + f - 64) * 256;
                float4 v = *(const float4*)(wrow + kc * 32 + c4 * 4);
                float* d = ws + f * WSP + c4 * 4;
                d[0] = tfr(v.x); d[1] = tfr(v.y); d[2] = tfr(v.z); d[3] = tfr(v.w);
            }
            __syncthreads();
            #pragma unroll
            for (int j = 0; j < 3; j++) {
                int id = w + 8 * j;
                int mi = id / 6, ni = id % 6;
                #pragma unroll
                for (int k8 = 0; k8 < 4; k8++) {
                    FragA fa; FragBc fb;
                    wmma::load_matrix_sync(fa, xs + mi * 16 * XP + kc * 32 + k8 * 8, XP);
                    wmma::load_matrix_sync(fb, ws + ni * 16 * WSP + k8 * 8, WSP);
                    wmma::mma_sync(acc[j], fa, fb, acc[j]);
                }
            }
        }
        #pragma unroll
        for (int j = 0; j < 3; j++) {
            int id = w + 8 * j;
            int mi = id / 6, ni = id % 6;
            wmma::store_matrix_sync(qk + mi * 16 * QKP + ni * 16, acc[j], QKP, wmma::mem_row_major);
        }
        __syncthreads();

        // bias fixup (+ SCALE on q), tf32 round
        #pragma unroll
        for (int i = 0; i < 24; i++) {
            int idx = tid + 256 * i;
            int t = idx / 96, c = idx % 96;
            float v = qk[t * QKP + c];
            if (c < 32)      v = (v + __ldg(bq  + h * 32 + c)) * SCALE_F;
            else if (c < 64) v = v + __ldg(bkv + h * 32 + c - 32);
            else             v = v + __ldg(bkv + 256 + h * 32 + c - 64);
            qk[t * QKP + c] = tfr(v);
        }
        __syncthreads();

        // ---- GEMM2: S[64,64] = Q K^T ----
        #pragma unroll
        for (int j = 0; j < 2; j++) {
            int id = w + 8 * j;
            int mi = id >> 2, ni = id & 3;
            FragC c2; wmma::fill_fragment(c2, 0.f);
            #pragma unroll
            for (int k8 = 0; k8 < 4; k8++) {
                FragA fa; FragBc fb;
                wmma::load_matrix_sync(fa, qk + mi * 16 * QKP + k8 * 8, QKP);
                wmma::load_matrix_sync(fb, qk + ni * 16 * QKP + 32 + k8 * 8, QKP);
                wmma::mma_sync(c2, fa, fb, c2);
            }
            wmma::store_matrix_sync(ss + mi * 16 * SSP + ni * 16, c2, SSP, wmma::mem_row_major);
        }
        __syncthreads();

        // ---- softmax: 4 threads/row ----
        {
            int n = tid >> 2, q = tid & 3;
            float*         srow = ss + n * SSP + q * 16;
            const float*   mrow = mk + n * MKP + q * 16;
            const uint8_t* rrow = ri + n * 65  + q * 16;
            float vb[16];
            float mx = -1e30f;
            #pragma unroll
            for (int m = 0; m < 16; m++) {
                float v = srow[m] + __ldg(btab + (int)rrow[m] * 8 + h) + mrow[m];
                vb[m] = v;
                mx = fmaxf(mx, v);
            }
            mx = fmaxf(mx, __shfl_xor_sync(0xffffffffu, mx, 1));
            mx = fmaxf(mx, __shfl_xor_sync(0xffffffffu, mx, 2));
            float s = 0.f;
            #pragma unroll
            for (int m = 0; m < 16; m++) {
                float p = __expf(vb[m] - mx);
                vb[m] = p;
                s += p;
            }
            s += __shfl_xor_sync(0xffffffffu, s, 1);
            s += __shfl_xor_sync(0xffffffffu, s, 2);
            float inv = 1.f / s;
            #pragma unroll
            for (int m = 0; m < 16; m++) srow[m] = tfr(vb[m] * inv);
        }
        __syncthreads();

        // ---- GEMM3: O_h[64,32] = P @ V ----
        {
            int mi = w >> 1, ni = w & 1;
            FragC c3; wmma::fill_fragment(c3, 0.f);
            #pragma unroll
            for (int k8 = 0; k8 < 8; k8++) {
                FragA fa; FragBr fb;
                wmma::load_matrix_sync(fa, ss + mi * 16 * SSP + k8 * 8, SSP);
                wmma::load_matrix_sync(fb, qk + (k8 * 8) * QKP + 64 + ni * 16, QKP);
                wmma::mma_sync(c3, fa, fb, c3);
            }
            wmma::store_matrix_sync(ob + mi * 16 * OBP + h * 32 + ni * 16, c3, OBP, wmma::mem_row_major);
        }
        __syncthreads();
        // round this head's O columns to tf32
        #pragma unroll
        for (int i = 0; i < 8; i++) {
            int idx = tid + 256 * i;
            int t = idx >> 5, c = idx & 31;
            ob[t * OBP + h * 32 + c] = tfr(ob[t * OBP + h * 32 + c]);
        }
        __syncthreads();
    }

    // ---- GEMM4: out[64,256] = Ob @ wp^T (staged into xs) ----
    for (int oc = 0; oc < 2; oc++) {
        FragC a5[4];
        #pragma unroll
        for (int j = 0; j < 4; j++) wmma::fill_fragment(a5[j], 0.f);

        for (int kc = 0; kc < 8; kc++) {
            __syncthreads();
            #pragma unroll
            for (int i = 0; i < 4; i++) {             // 128 rows x 32 cols
                int idx = tid + 256 * i;
                int f = idx >> 3, c4 = idx & 7;
                float4 v = *(const float4*)(wp + (size_t)(oc * 128 + f) * 256 + kc * 32 + c4 * 4);
                float* d = ws + f * WSP + c4 * 4;
                d[0] = tfr(v.x); d[1] = tfr(v.y); d[2] = tfr(v.z); d[3] = tfr(v.w);
            }
            __syncthreads();
            #pragma unroll
            for (int j = 0; j < 4; j++) {
                int id = w + 8 * j;
                int mi = id >> 3, ni = id & 7;
                #pragma unroll
                for (int k8 = 0; k8 < 4; k8++) {
                    FragA fa; FragBc fb;
                    wmma::load_matrix_sync(fa, ob + mi * 16 * OBP + kc * 32 + k8 * 8, OBP);
                    wmma::load_matrix_sync(fb, ws + ni * 16 * WSP + k8 * 8, WSP);
                    wmma::mma_sync(a5[j], fa, fb, a5[j]);
                }
            }
        }
        #pragma unroll
        for (int j = 0; j < 4; j++) {
            int id = w + 8 * j;
            int mi = id >> 3, ni = id & 7;
            wmma::store_matrix_sync(xs + mi * 16 * XP + oc * 128 + ni * 16, a5[j], XP, wmma::mem_row_major);
        }
    }
    __syncthreads();

    // ---- epilogue: + bp, coalesced store ----
    {
        float* og = out + (size_t)b * 16384;
        #pragma unroll
        for (int i = 0; i < 16; i++) {
            int idx = tid + 256 * i;
            int t = idx >> 6, c4 = idx & 63;
            const float* s = xs + t * XP + c4 * 4;
            float4 o;
            o.x = s[0] + __ldg(bp + c4 * 4 + 0);
            o.y = s[1] + __ldg(bp + c4 * 4 + 1);
            o.z = s[2] + __ldg(bp + c4 * 4 + 2);
            o.w = s[3] + __ldg(bp + c4 * 4 + 3);
            *(float4*)(og + t * 256 + c4 * 4) = o;
        }
    }
}

extern "C" void kernel_launch(void* const* d_in, const int* in_sizes, int n_in,
                              void* d_out, int out_size)
{
    const float* x    = (const float*)d_in[0];
    const float* mask = (const float*)d_in[1];
    const float* wq   = (const float*)d_in[2];
    const float* bq   = (const float*)d_in[3];
    const float* wkv  = (const float*)d_in[4];
    const float* bkv  = (const float*)d_in[5];
    const float* wp   = (const float*)d_in[6];
    const float* bp   = (const float*)d_in[7];
    const float* bt   = (const float*)d_in[8];
    const int*   ri   = (const int*)d_in[9];
    float* out = (float*)d_out;

    cudaFuncSetAttribute(winattn_wmma,
                         cudaFuncAttributeMaxDynamicSharedMemorySize, SMEM_BYTES);
    winattn_wmma<<<8192, 256, SMEM_BYTES>>>(x, mask, wq, bq, wkv, bkv, wp, bp, bt, ri, out);
}

// round 5
// speedup vs baseline: 6.6193x; 2.5030x over previous
#include <cuda_runtime.h>
#include <cuda_fp16.h>
#include <mma.h>
#include <cstdint>
using namespace nvcuda;

#define SCALE_F 0.17677669529663687f   // 32^-0.5

// half-precision smem pitches (elements)
#define XP  264   // X / [64][264] half
#define OBP 264   // attn-out [64][264] half
#define WSP 40    // weight chunk [96][40] half, x2 buffers
#define QKP 104   // qkv head [64][104] half
#define SPP 72    // fp32 scores / scratch [64][72]

#define SM_X   0u
#define SM_OB  33792u
#define SM_WS  67584u     // 2 x 96*40*2 = 15360
#define SM_QK  82944u
#define SM_SP  96256u     // 64*72*4 = 18432
#define SMEM_BYTES 114688u

typedef wmma::fragment<wmma::matrix_a, 16, 16, 16, __half, wmma::row_major> FragA;
typedef wmma::fragment<wmma::matrix_b, 16, 16, 16, __half, wmma::col_major> FragBc;
typedef wmma::fragment<wmma::matrix_b, 16, 16, 16, __half, wmma::row_major> FragBr;
typedef wmma::fragment<wmma::accumulator, 16, 16, 16, float> FragC;

__global__ __launch_bounds__(256, 2)
void winattn_h16(const float* __restrict__ x,    const float* __restrict__ mask,
                 const float* __restrict__ wq,   const float* __restrict__ bq,
                 const float* __restrict__ wkv,  const float* __restrict__ bkv,
                 const float* __restrict__ wp,   const float* __restrict__ bp,
                 const float* __restrict__ btab, const int* __restrict__ ridx,
                 float* __restrict__ out)
{
    extern __shared__ char smem[];
    __half* xs = (__half*)(smem + SM_X);
    __half* ob = (__half*)(smem + SM_OB);
    __half* ws0 = (__half*)(smem + SM_WS);
    __half* ws1 = ws0 + 96 * WSP;
    __half* qk = (__half*)(smem + SM_QK);
    float*  sp = (float*)(smem + SM_SP);
    __half* ph = (__half*)(smem + SM_SP);       // P overlay on sp (with sync)
    float*  d3 = (float*)(smem + SM_WS);        // GEMM3 fp32 scratch (reuses ws)

    const int tid = threadIdx.x;
    const int w   = tid >> 5;
    const int b   = blockIdx.x;

    // ---------- stage X as fp16 ----------
    const float4* xg = (const float4*)(x + (size_t)b * 16384);
    #pragma unroll
    for (int i = 0; i < 16; i++) {
        int idx = tid + 256 * i;
        int t = idx >> 6, c4 = idx & 63;
        float4 v = xg[idx];
        __half2* d = (__half2*)(xs + t * XP + c4 * 4);
        d[0] = __floats2half2_rn(v.x, v.y);
        d[1] = __floats2half2_rn(v.z, v.w);
    }
    __syncthreads();

    const int f96  = tid >> 5;           // staging row helper GEMM1 (12 rows apart)
    const int kk32 = tid & 31;

    // ---------- per-head ----------
    for (int h = 0; h < 8; h++) {
        // ---- GEMM1: QKV_h[64,96] = X @ W_h^T  (q-scale folded into Wq) ----
        FragC acc[3];
        #pragma unroll
        for (int j = 0; j < 3; j++) wmma::fill_fragment(acc[j], 0.f);

        float pre[12];
        #pragma unroll
        for (int i = 0; i < 12; i++) {
            int f = f96 + 8 * i;
            const float* wrow =
                (f < 32) ? wq  + (size_t)(h * 32 + f) * 256 :
                (f < 64) ? wkv + (size_t)(h * 32 + f - 32) * 256
                         : wkv + (size_t)(256 + h * 32 + f - 64) * 256;
            float v = __ldg(wrow + kk32);
            pre[i] = (f < 32) ? v * SCALE_F : v;
        }
        for (int kc = 0; kc < 8; kc++) {
            __half* wb = (kc & 1) ? ws1 : ws0;
            #pragma unroll
            for (int i = 0; i < 12; i++)
                wb[(f96 + 8 * i) * WSP + kk32] = __float2half_rn(pre[i]);
            __syncthreads();
            if (kc < 7) {
                #pragma unroll
                for (int i = 0; i < 12; i++) {
                    int f = f96 + 8 * i;
                    const float* wrow =
                        (f < 32) ? wq  + (size_t)(h * 32 + f) * 256 :
                        (f < 64) ? wkv + (size_t)(h * 32 + f - 32) * 256
                                 : wkv + (size_t)(256 + h * 32 + f - 64) * 256;
                    float v = __ldg(wrow + (kc + 1) * 32 + kk32);
                    pre[i] = (f < 32) ? v * SCALE_F : v;
                }
            }
            #pragma unroll
            for (int j = 0; j < 3; j++) {
                int id = w + 8 * j;
                int mi = id / 6, ni = id % 6;
                #pragma unroll
                for (int k8 = 0; k8 < 2; k8++) {
                    FragA fa; FragBc fb;
                    wmma::load_matrix_sync(fa, xs + mi * 16 * XP + kc * 32 + k8 * 16, XP);
                    wmma::load_matrix_sync(fb, wb + ni * 16 * WSP + k8 * 16, WSP);
                    wmma::mma_sync(acc[j], fa, fb, acc[j]);
                }
            }
        }
        __syncthreads();

        // ---- fixup to qk half in 2 batches of 48 cols (bias add) ----
        #pragma unroll
        for (int bb = 0; bb < 2; bb++) {
            int cb = bb * 48;   // tiles ni in [3bb, 3bb+3)
            #pragma unroll
            for (int j = 0; j < 3; j++) {
                int id = w + 8 * j;
                int mi = id / 6, ni = id % 6;
                if (ni >= 3 * bb && ni < 3 * bb + 3)
                    wmma::store_matrix_sync(sp + mi * 16 * SPP + (ni - 3 * bb) * 16,
                                            acc[j], SPP, wmma::mem_row_major);
            }
            __syncthreads();
            #pragma unroll
            for (int i = 0; i < 12; i++) {
                int idx = tid + 256 * i;
                int t = idx / 48, c = idx % 48;
                int col = cb + c;
                float bias;
                if (col < 32)      bias = __ldg(bq  + h * 32 + col) * SCALE_F;
                else if (col < 64) bias = __ldg(bkv + h * 32 + col - 32);
                else               bias = __ldg(bkv + 256 + h * 32 + col - 64);
                qk[t * QKP + col] = __float2half_rn(sp[t * SPP + c] + bias);
            }
            __syncthreads();
        }

        // ---- GEMM2: S[64,64] = Q K^T -> sp fp32 ----
        #pragma unroll
        for (int j = 0; j < 2; j++) {
            int id = w + 8 * j;
            int mi = id >> 2, ni = id & 3;
            FragC c2; wmma::fill_fragment(c2, 0.f);
            #pragma unroll
            for (int k8 = 0; k8 < 2; k8++) {
                FragA fa; FragBc fb;
                wmma::load_matrix_sync(fa, qk + mi * 16 * QKP + k8 * 16, QKP);
                wmma::load_matrix_sync(fb, qk + ni * 16 * QKP + 32 + k8 * 16, QKP);
                wmma::mma_sync(c2, fa, fb, c2);
            }
            wmma::store_matrix_sync(sp + mi * 16 * SPP + ni * 16, c2, SPP, wmma::mem_row_major);
        }
        __syncthreads();

        // ---- softmax: 4 threads/row; bias+mask straight from L2 ----
        {
            int n = tid >> 2, q = tid & 3;
            const float* srow = sp + n * SPP + q * 16;
            const float* mrow = mask + (size_t)(b & 4095) * 4096 + n * 64 + q * 16;
            const int*   rrow = ridx + n * 64 + q * 16;
            float vb[16];
            float mx = -1e30f;
            #pragma unroll
            for (int m = 0; m < 16; m++) {
                float v = srow[m] + __ldg(btab + __ldg(rrow + m) * 8 + h) + __ldg(mrow + m);
                vb[m] = v;
                mx = fmaxf(mx, v);
            }
            mx = fmaxf(mx, __shfl_xor_sync(0xffffffffu, mx, 1));
            mx = fmaxf(mx, __shfl_xor_sync(0xffffffffu, mx, 2));
            float s = 0.f;
            #pragma unroll
            for (int m = 0; m < 16; m++) {
                float p = __expf(vb[m] - mx);
                vb[m] = p;
                s += p;
            }
            s += __shfl_xor_sync(0xffffffffu, s, 1);
            s += __shfl_xor_sync(0xffffffffu, s, 2);
            float inv = 1.f / s;
            __syncthreads();   // all score reads done before P overlay write
            #pragma unroll
            for (int m = 0; m < 16; m++)
                ph[n * SPP + q * 16 + m] = __float2half_rn(vb[m] * inv);
        }
        __syncthreads();

        // ---- GEMM3: O_h[64,32] = P @ V -> d3 fp32 -> ob half ----
        {
            int mi = w >> 1, ni = w & 1;
            FragC c3; wmma::fill_fragment(c3, 0.f);
            #pragma unroll
            for (int k8 = 0; k8 < 4; k8++) {
                FragA fa; FragBr fb;
                wmma::load_matrix_sync(fa, ph + mi * 16 * SPP + k8 * 16, SPP);
                wmma::load_matrix_sync(fb, qk + (k8 * 16) * QKP + 64 + ni * 16, QKP);
                wmma::mma_sync(c3, fa, fb, c3);
            }
            wmma::store_matrix_sync(d3 + mi * 16 * 40 + ni * 16, c3, 40, wmma::mem_row_major);
        }
        __syncthreads();
        #pragma unroll
        for (int i = 0; i < 8; i++) {
            int idx = tid + 256 * i;
            int t = idx >> 5, c = idx & 31;
            ob[t * OBP + h * 32 + c] = __float2half_rn(d3[t * 40 + c]);
        }
        __syncthreads();
    }

    // ---------- GEMM4: out[64,256] = Ob @ wp^T, 4 col-groups of 64 ----------
    const int f64 = tid >> 5;   // 8 rows apart
    for (int oc = 0; oc < 4; oc++) {
        FragC a4[2];
        #pragma unroll
        for (int j = 0; j < 2; j++) wmma::fill_fragment(a4[j], 0.f);

        float pre4[8];
        #pragma unroll
        for (int i = 0; i < 8; i++)
            pre4[i] = __ldg(wp + (size_t)(oc * 64 + f64 + 8 * i) * 256 + kk32);
        for (int kc = 0; kc < 8; kc++) {
            __half* wb = (kc & 1) ? ws1 : ws0;
            #pragma unroll
            for (int i = 0; i < 8; i++)
                wb[(f64 + 8 * i) * WSP + kk32] = __float2half_rn(pre4[i]);
            __syncthreads();
            if (kc < 7) {
                #pragma unroll
                for (int i = 0; i < 8; i++)
                    pre4[i] = __ldg(wp + (size_t)(oc * 64 + f64 + 8 * i) * 256 + (kc + 1) * 32 + kk32);
            }
            #pragma unroll
            for (int j = 0; j < 2; j++) {
                int id = w + 8 * j;
                int mi = id >> 2, ni = id & 3;
                #pragma unroll
                for (int k8 = 0; k8 < 2; k8++) {
                    FragA fa; FragBc fb;
                    wmma::load_matrix_sync(fa, ob + mi * 16 * OBP + kc * 32 + k8 * 16, OBP);
                    wmma::load_matrix_sync(fb, wb + ni * 16 * WSP + k8 * 16, WSP);
                    wmma::mma_sync(a4[j], fa, fb, a4[j]);
                }
            }
        }
        __syncthreads();
        #pragma unroll
        for (int j = 0; j < 2; j++) {
            int id = w + 8 * j;
            int mi = id >> 2, ni = id & 3;
            wmma::store_matrix_sync(sp + mi * 16 * SPP + ni * 16, a4[j], SPP, wmma::mem_row_major);
        }
        __syncthreads();
        // epilogue: +bp, float4 store
        float* og = out + (size_t)b * 16384 + oc * 64;
        #pragma unroll
        for (int i = 0; i < 4; i++) {
            int idx = tid + 256 * i;
            int t = idx >> 4, c4 = idx & 15;
            const float* s = sp + t * SPP + c4 * 4;
            float4 o;
            o.x = s[0] + __ldg(bp + oc * 64 + c4 * 4 + 0);
            o.y = s[1] + __ldg(bp + oc * 64 + c4 * 4 + 1);
            o.z = s[2] + __ldg(bp + oc * 64 + c4 * 4 + 2);
            o.w = s[3] + __ldg(bp + oc * 64 + c4 * 4 + 3);
            *(float4*)(og + t * 256 + c4 * 4) = o;
        }
        __syncthreads();
    }
}

extern "C" void kernel_launch(void* const* d_in, const int* in_sizes, int n_in,
                              void* d_out, int out_size)
{
    const float* x    = (const float*)d_in[0];
    const float* mask = (const float*)d_in[1];
    const float* wq   = (const float*)d_in[2];
    const float* bq   = (const float*)d_in[3];
    const float* wkv  = (const float*)d_in[4];
    const float* bkv  = (const float*)d_in[5];
    const float* wp   = (const float*)d_in[6];
    const float* bp   = (const float*)d_in[7];
    const float* bt   = (const float*)d_in[8];
    const int*   ri   = (const int*)d_in[9];
    float* out = (float*)d_out;

    cudaFuncSetAttribute(winattn_h16,
                         cudaFuncAttributeMaxDynamicSharedMemorySize, SMEM_BYTES);
    winattn_h16<<<8192, 256, SMEM_BYTES>>>(x, mask, wq, bq, wkv, bkv, wp, bp, bt, ri, out);
}

// round 6
// speedup vs baseline: 8.3811x; 1.2662x over previous
#include <cuda_runtime.h>
#include <cuda_fp16.h>
#include <mma.h>
#include <cstdint>
using namespace nvcuda;

#define SCALE_F 0.17677669529663687f   // 32^-0.5

// prepacked weights (device scratch)
__device__ __half g_w1[8 * 96 * 256];   // per-head fused [q(scaled)|k|v][256]
__device__ __half g_w4[256 * 256];      // wp as half
__device__ float  g_bf[8 * 64 * 64];    // btab[rel_idx] per head
__device__ float  g_b1v[8 * 96];        // fused bias (q part scaled)

// smem layout (elements)
#define XP  264
#define OBP 264
#define WSP 40
#define QKP 104
#define SPP 72
#define SM_X   0u
#define SM_OB  33792u
#define SM_WS  67584u     // 2 x 96*40*2 = 15360 (also GEMM3 fp32 scratch)
#define SM_QK  82944u
#define SM_SP  96256u
#define SMEM_BYTES 114688u

typedef wmma::fragment<wmma::matrix_a, 16, 16, 16, __half, wmma::row_major> FragA;
typedef wmma::fragment<wmma::matrix_b, 16, 16, 16, __half, wmma::col_major> FragBc;
typedef wmma::fragment<wmma::matrix_b, 16, 16, 16, __half, wmma::row_major> FragBr;
typedef wmma::fragment<wmma::accumulator, 16, 16, 16, float> FragC;

__device__ __forceinline__ uint32_t smem_u32(const void* p) {
    uint32_t a;
    asm("{ .reg .u64 t; cvta.to.shared.u64 t, %1; cvt.u32.u64 %0, t; }" : "=r"(a) : "l"(p));
    return a;
}
__device__ __forceinline__ void cp16(uint32_t dst, const void* src) {
    asm volatile("cp.async.ca.shared.global [%0], [%1], 16;" :: "r"(dst), "l"(src));
}
#define CP_COMMIT() asm volatile("cp.async.commit_group;" ::: "memory")
#define CP_WAIT0()  asm volatile("cp.async.wait_group 0;" ::: "memory")

// ---------------- prep kernel: pack weights to fp16 / pre-gather bias ----------------
__global__ void prep_kernel(const float* __restrict__ wq,  const float* __restrict__ bq,
                            const float* __restrict__ wkv, const float* __restrict__ bkv,
                            const float* __restrict__ wp,
                            const float* __restrict__ btab, const int* __restrict__ ridx)
{
    int idx = blockIdx.x * 256 + threadIdx.x;
    if (idx < 196608) {                       // g_w1
        int h = idx / 24576, r = idx % 24576;
        int f = r >> 8, c = r & 255;
        float v;
        if (f < 32)      v = wq[(size_t)(h * 32 + f) * 256 + c] * SCALE_F;
        else if (f < 64) v = wkv[(size_t)(h * 32 + f - 32) * 256 + c];
        else             v = wkv[(size_t)(256 + h * 32 + f - 64) * 256 + c];
        g_w1[idx] = __float2half_rn(v);
    } else if (idx < 262144) {                // g_w4
        int i = idx - 196608;
        g_w4[i] = __float2half_rn(wp[i]);
    } else if (idx < 294912) {                // g_bf
        int i = idx - 262144;
        int h = i >> 12, nm = i & 4095;
        g_bf[i] = btab[ridx[nm] * 8 + h];
    } else if (idx < 295680) {                // g_b1v
        int i = idx - 294912;
        int h = i / 96, f = i % 96;
        float v;
        if (f < 32)      v = bq[h * 32 + f] * SCALE_F;
        else if (f < 64) v = bkv[h * 32 + f - 32];
        else             v = bkv[256 + h * 32 + f - 64];
        g_b1v[i] = v;
    }
}

// ---------------- main kernel ----------------
__global__ __launch_bounds__(256, 2)
void winattn_h16b(const float* __restrict__ x, const float* __restrict__ mask,
                  const float* __restrict__ bp, float* __restrict__ out)
{
    extern __shared__ char smem[];
    __half* xs  = (__half*)(smem + SM_X);
    __half* ob  = (__half*)(smem + SM_OB);
    __half* ws0 = (__half*)(smem + SM_WS);
    __half* ws1 = ws0 + 96 * WSP;
    __half* qk  = (__half*)(smem + SM_QK);
    float*  sp  = (float*)(smem + SM_SP);
    __half* ph  = (__half*)(smem + SM_SP);   // P overlay (sync-protected)
    float*  d3  = (float*)(smem + SM_WS);    // GEMM3 fp32 scratch

    const uint32_t wsa0 = smem_u32(ws0);
    const uint32_t wsa1 = smem_u32(ws1);
    const int tid = threadIdx.x;
    const int w   = tid >> 5;
    const int b   = blockIdx.x;

    // stage X as fp16
    const float4* xg = (const float4*)(x + (size_t)b * 16384);
    #pragma unroll
    for (int i = 0; i < 16; i++) {
        int idx = tid + 256 * i;
        int t = idx >> 6, c4 = idx & 63;
        float4 v = xg[idx];
        __half2* d = (__half2*)(xs + t * XP + c4 * 4);
        d[0] = __floats2half2_rn(v.x, v.y);
        d[1] = __floats2half2_rn(v.z, v.w);
    }

    const int mi = w >> 1;          // warp tile row (0..3)
    const int nh = w & 1;           // warp tile col half

    for (int h = 0; h < 8; h++) {
        // ---- GEMM1: QKV_h[64,96] = X @ W1_h^T, cp.async double-buffered ----
        FragC acc[3];
        #pragma unroll
        for (int j = 0; j < 3; j++) wmma::fill_fragment(acc[j], 0.f);

        const __half* w1h = g_w1 + h * 24576;
        {   // prologue: chunk 0
            #pragma unroll
            for (int i = 0; i < 2; i++) {
                int idx = tid + 256 * i;
                if (idx < 384) {
                    int f = idx >> 2, p = idx & 3;
                    cp16(wsa0 + f * 80 + p * 16, w1h + f * 256 + p * 8);
                }
            }
            CP_COMMIT();
        }
        for (int kc = 0; kc < 8; kc++) {
            CP_WAIT0();
            __syncthreads();
            if (kc < 7) {
                uint32_t dst = (kc & 1) ? wsa0 : wsa1;
                #pragma unroll
                for (int i = 0; i < 2; i++) {
                    int idx = tid + 256 * i;
                    if (idx < 384) {
                        int f = idx >> 2, p = idx & 3;
                        cp16(dst + f * 80 + p * 16, w1h + f * 256 + (kc + 1) * 32 + p * 8);
                    }
                }
                CP_COMMIT();
            }
            __half* wb = (kc & 1) ? ws1 : ws0;
            #pragma unroll
            for (int k8 = 0; k8 < 2; k8++) {
                FragA fa;
                wmma::load_matrix_sync(fa, xs + mi * 16 * XP + kc * 32 + k8 * 16, XP);
                #pragma unroll
                for (int j = 0; j < 3; j++) {
                    FragBc fb;
                    wmma::load_matrix_sync(fb, wb + (nh * 3 + j) * 16 * WSP + k8 * 16, WSP);
                    wmma::mma_sync(acc[j], fa, fb, acc[j]);
                }
            }
        }
        __syncthreads();

        // ---- bias fixup to qk (2 batches of 48 cols) ----
        #pragma unroll
        for (int bb = 0; bb < 2; bb++) {
            if (nh == bb) {
                #pragma unroll
                for (int j = 0; j < 3; j++)
                    wmma::store_matrix_sync(sp + mi * 16 * SPP + j * 16, acc[j], SPP, wmma::mem_row_major);
            }
            __syncthreads();
            #pragma unroll
            for (int i = 0; i < 12; i++) {
                int idx = tid + 256 * i;
                int t = idx / 48, c = idx % 48;
                int col = bb * 48 + c;
                qk[t * QKP + col] = __float2half_rn(sp[t * SPP + c] + g_b1v[h * 96 + col]);
            }
            __syncthreads();
        }

        // ---- GEMM2: S = Q K^T ----
        {
            FragC c2[2];
            #pragma unroll
            for (int j = 0; j < 2; j++) wmma::fill_fragment(c2[j], 0.f);
            #pragma unroll
            for (int k8 = 0; k8 < 2; k8++) {
                FragA fa;
                wmma::load_matrix_sync(fa, qk + mi * 16 * QKP + k8 * 16, QKP);
                #pragma unroll
                for (int j = 0; j < 2; j++) {
                    FragBc fb;
                    wmma::load_matrix_sync(fb, qk + (nh * 2 + j) * 16 * QKP + 32 + k8 * 16, QKP);
                    wmma::mma_sync(c2[j], fa, fb, c2[j]);
                }
            }
            #pragma unroll
            for (int j = 0; j < 2; j++)
                wmma::store_matrix_sync(sp + mi * 16 * SPP + (nh * 2 + j) * 16, c2[j], SPP, wmma::mem_row_major);
        }
        __syncthreads();

        // ---- softmax: 4 threads/row ----
        {
            int n = tid >> 2, q = tid & 3;
            const float* srow = sp + n * SPP + q * 16;
            const float* brow = g_bf + (h * 64 + n) * 64 + q * 16;
            const float* mrow = mask + (size_t)(b & 4095) * 4096 + n * 64 + q * 16;
            float vb[16];
            float mx = -1e30f;
            #pragma unroll
            for (int m = 0; m < 16; m++) {
                float v = srow[m] + brow[m] + __ldg(mrow + m);
                vb[m] = v;
                mx = fmaxf(mx, v);
            }
            mx = fmaxf(mx, __shfl_xor_sync(0xffffffffu, mx, 1));
            mx = fmaxf(mx, __shfl_xor_sync(0xffffffffu, mx, 2));
            float s = 0.f;
            #pragma unroll
            for (int m = 0; m < 16; m++) {
                float p = __expf(vb[m] - mx);
                vb[m] = p;
                s += p;
            }
            s += __shfl_xor_sync(0xffffffffu, s, 1);
            s += __shfl_xor_sync(0xffffffffu, s, 2);
            float inv = 1.f / s;
            __syncthreads();
            #pragma unroll
            for (int m = 0; m < 16; m++)
                ph[n * SPP + q * 16 + m] = __float2half_rn(vb[m] * inv);
        }
        __syncthreads();

        // ---- GEMM3: O_h = P @ V ----
        {
            FragC c3; wmma::fill_fragment(c3, 0.f);
            #pragma unroll
            for (int k8 = 0; k8 < 4; k8++) {
                FragA fa; FragBr fb;
                wmma::load_matrix_sync(fa, ph + mi * 16 * SPP + k8 * 16, SPP);
                wmma::load_matrix_sync(fb, qk + (k8 * 16) * QKP + 64 + nh * 16, QKP);
                wmma::mma_sync(c3, fa, fb, c3);
            }
            wmma::store_matrix_sync(d3 + mi * 16 * 40 + nh * 16, c3, 40, wmma::mem_row_major);
        }
        __syncthreads();
        #pragma unroll
        for (int i = 0; i < 8; i++) {
            int idx = tid + 256 * i;
            int t = idx >> 5, c = idx & 31;
            ob[t * OBP + h * 32 + c] = __float2half_rn(d3[t * 40 + c]);
        }
        __syncthreads();
    }

    // ---------- GEMM4: out = Ob @ wp^T, 4 col groups of 64 ----------
    for (int oc = 0; oc < 4; oc++) {
        FragC a4[2];
        #pragma unroll
        for (int j = 0; j < 2; j++) wmma::fill_fragment(a4[j], 0.f);

        const __half* w4o = g_w4 + (size_t)oc * 64 * 256;
        {   // prologue chunk 0 (64 rows x 4 parts = 256 transfers)
            int f = tid >> 2, p = tid & 3;
            cp16(wsa0 + f * 80 + p * 16, w4o + f * 256 + p * 8);
            CP_COMMIT();
        }
        for (int kc = 0; kc < 8; kc++) {
            CP_WAIT0();
            __syncthreads();
            if (kc < 7) {
                uint32_t dst = (kc & 1) ? wsa0 : wsa1;
                int f = tid >> 2, p = tid & 3;
                cp16(dst + f * 80 + p * 16, w4o + f * 256 + (kc + 1) * 32 + p * 8);
                CP_COMMIT();
            }
            __half* wb = (kc & 1) ? ws1 : ws0;
            #pragma unroll
            for (int k8 = 0; k8 < 2; k8++) {
                FragA fa;
                wmma::load_matrix_sync(fa, ob + mi * 16 * OBP + kc * 32 + k8 * 16, OBP);
                #pragma unroll
                for (int j = 0; j < 2; j++) {
                    FragBc fb;
                    wmma::load_matrix_sync(fb, wb + (nh * 2 + j) * 16 * WSP + k8 * 16, WSP);
                    wmma::mma_sync(a4[j], fa, fb, a4[j]);
                }
            }
        }
        __syncthreads();
        #pragma unroll
        for (int j = 0; j < 2; j++)
            wmma::store_matrix_sync(sp + mi * 16 * SPP + (nh * 2 + j) * 16, a4[j], SPP, wmma::mem_row_major);
        __syncthreads();
        // epilogue: +bp, float4 store
        float* og = out + (size_t)b * 16384 + oc * 64;
        #pragma unroll
        for (int i = 0; i < 4; i++) {
            int idx = tid + 256 * i;
            int t = idx >> 4, c4 = idx & 15;
            const float* s = sp + t * SPP + c4 * 4;
            float4 o;
            o.x = s[0] + __ldg(bp + oc * 64 + c4 * 4 + 0);
            o.y = s[1] + __ldg(bp + oc * 64 + c4 * 4 + 1);
            o.z = s[2] + __ldg(bp + oc * 64 + c4 * 4 + 2);
            o.w = s[3] + __ldg(bp + oc * 64 + c4 * 4 + 3);
            *(float4*)(og + t * 256 + c4 * 4) = o;
        }
        __syncthreads();
    }
}

extern "C" void kernel_launch(void* const* d_in, const int* in_sizes, int n_in,
                              void* d_out, int out_size)
{
    const float* x    = (const float*)d_in[0];
    const float* mask = (const float*)d_in[1];
    const float* wq   = (const float*)d_in[2];
    const float* bq   = (const float*)d_in[3];
    const float* wkv  = (const float*)d_in[4];
    const float* bkv  = (const float*)d_in[5];
    const float* wp   = (const float*)d_in[6];
    const float* bp   = (const float*)d_in[7];
    const float* bt   = (const float*)d_in[8];
    const int*   ri   = (const int*)d_in[9];
    float* out = (float*)d_out;

    prep_kernel<<<1155, 256>>>(wq, bq, wkv, bkv, wp, bt, ri);
    cudaFuncSetAttribute(winattn_h16b,
                         cudaFuncAttributeMaxDynamicSharedMemorySize, SMEM_BYTES);
    winattn_h16b<<<8192, 256, SMEM_BYTES>>>(x, mask, bp, out);
}